// round 16
// baseline (speedup 1.0000x reference)
#include <cuda_runtime.h>
#include <cuda_fp16.h>
#include <stdint.h>

// ---------------- problem constants ----------------
#define NB   2
#define TT   2048
#define DM   2048
#define NH   16
#define HD   128
#define DFF  8192
#define TOK  (NB*TT)

// ---------------- scratch (device globals) ----------------
__device__ __half g_h1  [(size_t)TOK*DM];
__device__ __half g_q   [(size_t)TOK*DM];
__device__ __half g_k   [(size_t)TOK*DM];
__device__ __half g_v   [(size_t)TOK*DM];
__device__ __half g_vT  [(size_t)TOK*DM];
__device__ float  g_sc  [(size_t)NB*NH*TT*TT];   // fp32 scores
__device__ __half g_scp [(size_t)NB*NH*TT*TT];   // fp16 probs
__device__ __half g_attn[(size_t)TOK*DM];
__device__ float  g_x1  [(size_t)TOK*DM];
__device__ __half g_h2  [(size_t)TOK*DM];
__device__ float  g_gate[(size_t)TOK*DFF];
__device__ __half g_ff  [(size_t)TOK*DFF];
__device__ __half g_wq[(size_t)DM*DM];
__device__ __half g_wk[(size_t)DM*DM];
__device__ __half g_wv[(size_t)DM*DM];
__device__ __half g_wo[(size_t)DM*DM];
__device__ __half g_wg[(size_t)DFF*DM];
__device__ __half g_wu[(size_t)DFF*DM];
__device__ __half g_wd[(size_t)DM*DFF];

// ---------------- helpers ----------------
__device__ __forceinline__ void cpasync16(void* dst, const void* src) {
    uint32_t s = (uint32_t)__cvta_generic_to_shared(dst);
    asm volatile("cp.async.cg.shared.global [%0], [%1], 16;\n" :: "r"(s), "l"(src));
}

__device__ __forceinline__ void ldsm_x4(uint32_t& r0, uint32_t& r1,
                                        uint32_t& r2, uint32_t& r3, uint32_t addr) {
    asm volatile("ldmatrix.sync.aligned.m8n8.x4.shared.b16 {%0,%1,%2,%3}, [%4];"
                 : "=r"(r0), "=r"(r1), "=r"(r2), "=r"(r3) : "r"(addr));
}

// ---------------- fp16 tensor-core GEMM ----------------
// 128x128 CTA tile, 128 threads: 4 warps in 2x2 grid, each warp 64(M)x64(N).
// 2 CTAs/SM. C[m,n] = scale * sum_k A[m,k]*B[n,k]
// epi=1 (OUTH=0): += Res.   epi=2 (OUTH=1): C = silu(Res) * acc  (SwiGLU fuse)
#define BM  128
#define BN  128
#define BK  32
#define SROW 40                     // halves per smem row (32 + 8 pad)
#define ASTG_A (BM*SROW)            // 5120 halves
#define ASTG_B (BN*SROW)            // 5120 halves
#define STG_H  (ASTG_A + ASTG_B)    // 10240 halves per stage
#define NSTAGE 3
#define GEMM_SMEM_BYTES (NSTAGE*STG_H*2)   // 61,440 B

extern __shared__ __half s16[];

template<int OUTH>
__global__ __launch_bounds__(128, 2)
void gemm_f16(const __half* __restrict__ A, const __half* __restrict__ Bm,
              void* __restrict__ Cv, const float* __restrict__ Res,
              int K, int lda, int ldb, int ldc,
              long long zaLo, long long zaHi,
              long long zbLo, long long zbHi,
              long long zcLo, long long zcHi,
              int zdiv, float scale, int epi)
{
    long long zq = blockIdx.z / zdiv, zr = blockIdx.z % zdiv;
    A  += zq*zaHi + zr*zaLo;
    Bm += zq*zbHi + zr*zbLo;
    const long long coff = zq*zcHi + zr*zcLo;
    if (epi) Res += coff;

    const int m0 = blockIdx.y * BM;
    const int n0 = blockIdx.x * BN;

    const int tid  = threadIdx.x;
    const int lane = tid & 31;
    const int warp = tid >> 5;          // 0..3
    const int mb   = (warp & 1) * 64;   // warp 64(M) x 64(N)
    const int nb   = (warp >> 1) * 64;

    float acc[4][8][4];
#pragma unroll
    for (int i = 0; i < 4; i++)
#pragma unroll
        for (int j = 0; j < 8; j++)
#pragma unroll
            for (int l = 0; l < 4; l++) acc[i][j][l] = 0.f;

    const int nK = K / BK;   // >= 4 for all shapes here

    // ldmatrix lane-address offsets (bytes) within a stage
    const uint32_t s16u = (uint32_t)__cvta_generic_to_shared(s16);
    const int lrow  = lane & 15;
    const int lchnk = (lane >> 4) * 8;
    const uint32_t aoff = (uint32_t)(((mb + lrow) * SROW + lchnk) * 2);
    const uint32_t boff = (uint32_t)(ASTG_A * 2 + ((nb + lrow) * SROW + lchnk) * 2);
    const uint32_t mstep = 16 * SROW * 2;   // 16 rows in bytes

    auto load_stage = [&](int st, int kt) {
        const int k0 = kt * BK;
        __half* sa = s16 + st * STG_H;
        __half* sb = sa + ASTG_A;
#pragma unroll
        for (int i = 0; i < 4; i++) {          // A: 128 rows x 4 chunks
            int idx = tid + i * 128;           // 0..511
            int row = idx >> 2;
            int c8  = (idx & 3) << 3;
            cpasync16(&sa[row*SROW + c8], A + (size_t)(m0+row)*lda + k0 + c8);
        }
#pragma unroll
        for (int i = 0; i < 4; i++) {          // B: 128 rows x 4 chunks
            int idx = tid + i * 128;
            int row = idx >> 2;
            int c8  = (idx & 3) << 3;
            cpasync16(&sb[row*SROW + c8], Bm + (size_t)(n0+row)*ldb + k0 + c8);
        }
    };

    auto compute = [&](int slot) {
        const uint32_t stg = s16u + (uint32_t)(slot * STG_H * 2);
#pragma unroll
        for (int kk = 0; kk < BK; kk += 16) {
            const uint32_t kb = stg + kk * 2;
            uint32_t af[4][4];
#pragma unroll
            for (int im = 0; im < 4; im++)
                ldsm_x4(af[im][0], af[im][1], af[im][2], af[im][3],
                        kb + aoff + im * mstep);
            uint32_t bf[8][2];
#pragma unroll
            for (int p = 0; p < 4; p++)
                ldsm_x4(bf[2*p][0], bf[2*p+1][0], bf[2*p][1], bf[2*p+1][1],
                        kb + boff + p * mstep);
#pragma unroll
            for (int im = 0; im < 4; im++)
#pragma unroll
                for (int in = 0; in < 8; in++) {
                    asm volatile(
                        "mma.sync.aligned.m16n8k16.row.col.f32.f16.f16.f32 "
                        "{%0,%1,%2,%3}, {%4,%5,%6,%7}, {%8,%9}, {%0,%1,%2,%3};\n"
                        : "+f"(acc[im][in][0]), "+f"(acc[im][in][1]),
                          "+f"(acc[im][in][2]), "+f"(acc[im][in][3])
                        : "r"(af[im][0]), "r"(af[im][1]),
                          "r"(af[im][2]), "r"(af[im][3]),
                          "r"(bf[in][0]), "r"(bf[in][1]));
                }
        }
    };

    // prologue: 2 stages in flight (prefetch distance 2 <= NSTAGE-1)
    load_stage(0, 0);
    asm volatile("cp.async.commit_group;\n");
    load_stage(1, 1);
    asm volatile("cp.async.commit_group;\n");

    for (int kt = 0; kt < nK; kt++) {
        if (kt + 1 < nK) asm volatile("cp.async.wait_group 1;\n");
        else             asm volatile("cp.async.wait_group 0;\n");
        __syncthreads();

        if (kt + 2 < nK) {
            load_stage((kt + 2) % NSTAGE, kt + 2);   // targets retired slot (kt-1)%3
            asm volatile("cp.async.commit_group;\n");
        }

        compute(kt % NSTAGE);
    }

    // epilogue
#pragma unroll
    for (int im = 0; im < 4; im++) {
#pragma unroll
        for (int in = 0; in < 8; in++) {
            int r = m0 + mb + im*16 + (lane >> 2);
            int c = n0 + nb + in*8 + ((lane & 3) << 1);
            float v0 = acc[im][in][0] * scale;
            float v1 = acc[im][in][1] * scale;
            float v2 = acc[im][in][2] * scale;
            float v3 = acc[im][in][3] * scale;
            if (OUTH) {
                if (epi == 2) {   // SwiGLU: C = silu(Res) * acc
                    float2 r0 = *(const float2*)&Res[(size_t)(r  )*ldc + c];
                    float2 r1 = *(const float2*)&Res[(size_t)(r+8)*ldc + c];
                    v0 *= r0.x / (1.f + __expf(-r0.x));
                    v1 *= r0.y / (1.f + __expf(-r0.y));
                    v2 *= r1.x / (1.f + __expf(-r1.x));
                    v3 *= r1.y / (1.f + __expf(-r1.y));
                }
                __half* C = (__half*)Cv + coff;
                *(__half2*)&C[(size_t)(r  )*ldc + c] = __floats2half2_rn(v0, v1);
                *(__half2*)&C[(size_t)(r+8)*ldc + c] = __floats2half2_rn(v2, v3);
            } else {
                float* C = (float*)Cv + coff;
                float2 t0 = {v0, v1}, t1 = {v2, v3};
                if (epi == 1) {
                    float2 r0 = *(const float2*)&Res[(size_t)(r  )*ldc + c];
                    float2 r1 = *(const float2*)&Res[(size_t)(r+8)*ldc + c];
                    t0.x += r0.x; t0.y += r0.y;
                    t1.x += r1.x; t1.y += r1.y;
                }
                *(float2*)&C[(size_t)(r  )*ldc + c] = t0;
                *(float2*)&C[(size_t)(r+8)*ldc + c] = t1;
            }
        }
    }
}

// ---------------- merged weight conversion f32 -> f16 ----------------
#define S4 (DM*DM/4)
#define L4 (DFF*DM/4)
__global__ __launch_bounds__(256)
void cvt_all_kernel(const float* __restrict__ wq, const float* __restrict__ wk,
                    const float* __restrict__ wv, const float* __restrict__ wo,
                    const float* __restrict__ wg, const float* __restrict__ wu,
                    const float* __restrict__ wd,
                    __half* __restrict__ oq, __half* __restrict__ ok,
                    __half* __restrict__ ov, __half* __restrict__ oo,
                    __half* __restrict__ og, __half* __restrict__ ou,
                    __half* __restrict__ od)
{
    int i = blockIdx.x * 256 + threadIdx.x;
    const float* src; __half* dst; int off;
    if (i < 4*S4) {
        int w = i / S4; off = i - w*S4;
        src = (w == 0) ? wq : (w == 1) ? wk : (w == 2) ? wv : wo;
        dst = (w == 0) ? oq : (w == 1) ? ok : (w == 2) ? ov : oo;
    } else {
        int j = i - 4*S4;
        int w = j / L4; off = j - w*L4;
        src = (w == 0) ? wg : (w == 1) ? wu : wd;
        dst = (w == 0) ? og : (w == 1) ? ou : od;
    }
    float4 v = ((const float4*)src)[off];
    ((__half2*)dst)[2*off    ] = __floats2half2_rn(v.x, v.y);
    ((__half2*)dst)[2*off + 1] = __floats2half2_rn(v.z, v.w);
}

// ---------------- LayerNorm (half output) ----------------
__global__ __launch_bounds__(256)
void ln_kernel(const float* __restrict__ x, const float* __restrict__ w,
               const float* __restrict__ b, __half* __restrict__ y)
{
    const int row = blockIdx.x;
    const float* xr = x + (size_t)row * DM;
    __half*      yr = y + (size_t)row * DM;

    float s = 0.f, sq = 0.f;
#pragma unroll
    for (int i = 0; i < DM/256; i++) {
        float v = xr[threadIdx.x + i*256];
        s += v; sq += v*v;
    }
#pragma unroll
    for (int o = 16; o; o >>= 1) {
        s  += __shfl_xor_sync(0xffffffffu, s,  o);
        sq += __shfl_xor_sync(0xffffffffu, sq, o);
    }
    __shared__ float sh[64];
    const int warp = threadIdx.x >> 5, lane = threadIdx.x & 31;
    if (lane == 0) { sh[warp] = s; sh[warp + 32] = sq; }
    __syncthreads();
    if (warp == 0) {
        s  = (lane < 8) ? sh[lane]      : 0.f;
        sq = (lane < 8) ? sh[lane + 32] : 0.f;
#pragma unroll
        for (int o = 4; o; o >>= 1) {
            s  += __shfl_xor_sync(0xffffffffu, s,  o);
            sq += __shfl_xor_sync(0xffffffffu, sq, o);
        }
        if (lane == 0) { sh[0] = s; sh[1] = sq; }
    }
    __syncthreads();
    const float mean = sh[0] * (1.f/DM);
    const float var  = sh[1] * (1.f/DM) - mean*mean;
    const float inv  = rsqrtf(var + 1e-5f);
#pragma unroll
    for (int i = 0; i < DM/256; i++) {
        int c = threadIdx.x + i*256;
        yr[c] = __float2half_rn((xr[c] - mean) * inv * w[c] + b[c]);
    }
}

// ---------------- softmax: fp32 scores -> fp16 probs ----------------
__global__ __launch_bounds__(256)
void softmax_kernel(const float* __restrict__ s, __half* __restrict__ p)
{
    const float* r = s + (size_t)blockIdx.x * TT;
    __half*      o = p + (size_t)blockIdx.x * TT;
    float v[TT/256];
    float mx = -1e30f;
#pragma unroll
    for (int i = 0; i < TT/256; i++) {
        v[i] = r[threadIdx.x + i*256];
        mx = fmaxf(mx, v[i]);
    }
#pragma unroll
    for (int ofs = 16; ofs; ofs >>= 1) mx = fmaxf(mx, __shfl_xor_sync(0xffffffffu, mx, ofs));
    __shared__ float sh[32];
    const int warp = threadIdx.x >> 5, lane = threadIdx.x & 31;
    if (lane == 0) sh[warp] = mx;
    __syncthreads();
    if (warp == 0) {
        mx = (lane < 8) ? sh[lane] : -1e30f;
#pragma unroll
        for (int ofs = 4; ofs; ofs >>= 1) mx = fmaxf(mx, __shfl_xor_sync(0xffffffffu, mx, ofs));
        if (lane == 0) sh[0] = mx;
    }
    __syncthreads();
    mx = sh[0];

    float sum = 0.f;
#pragma unroll
    for (int i = 0; i < TT/256; i++) { v[i] = __expf(v[i] - mx); sum += v[i]; }
#pragma unroll
    for (int ofs = 16; ofs; ofs >>= 1) sum += __shfl_xor_sync(0xffffffffu, sum, ofs);
    if (lane == 0) sh[warp] = sum;
    __syncthreads();
    if (warp == 0) {
        sum = (lane < 8) ? sh[lane] : 0.f;
#pragma unroll
        for (int ofs = 4; ofs; ofs >>= 1) sum += __shfl_xor_sync(0xffffffffu, sum, ofs);
        if (lane == 0) sh[0] = sum;
    }
    __syncthreads();
    const float inv = 1.f / sh[0];
#pragma unroll
    for (int i = 0; i < TT/256; i++)
        o[threadIdx.x + i*256] = __float2half_rn(v[i] * inv);
}

// ---------------- V -> V^T per batch (half) ----------------
__global__ void transpose_v_kernel(const __half* __restrict__ v, __half* __restrict__ vt)
{
    __shared__ __half tile[32][34];
    const int b  = blockIdx.z;
    const int x0 = blockIdx.x * 32;
    const int y0 = blockIdx.y * 32;
    const __half* vb = v  + (size_t)b * TT * DM;
    __half*      vtb = vt + (size_t)b * TT * DM;
    const int tx = threadIdx.x, ty = threadIdx.y;
#pragma unroll
    for (int i = 0; i < 32; i += 8)
        tile[ty + i][tx] = vb[(size_t)(y0 + ty + i) * DM + x0 + tx];
    __syncthreads();
#pragma unroll
    for (int i = 0; i < 32; i += 8)
        vtb[(size_t)(x0 + ty + i) * TT + y0 + tx] = tile[tx][ty + i];
}

// ---------------- launch ----------------
extern "C" void kernel_launch(void* const* d_in, const int* in_sizes, int n_in,
                              void* d_out, int out_size)
{
    const float* x     = (const float*)d_in[0];
    const float* wq    = (const float*)d_in[1];
    const float* wk    = (const float*)d_in[2];
    const float* wv    = (const float*)d_in[3];
    const float* wo    = (const float*)d_in[4];
    const float* wg    = (const float*)d_in[5];
    const float* wu    = (const float*)d_in[6];
    const float* wd    = (const float*)d_in[7];
    const float* ln1w  = (const float*)d_in[8];
    const float* ln1b  = (const float*)d_in[9];
    const float* ln2w  = (const float*)d_in[10];
    const float* ln2b  = (const float*)d_in[11];
    float* out = (float*)d_out;

    __half *h1, *q, *k, *v, *vt, *scp, *attn, *h2, *ff;
    float  *sc, *x1, *gate;
    __half *rwq, *rwk, *rwv, *rwo, *rwg, *rwu, *rwd;
    cudaGetSymbolAddress((void**)&h1,   g_h1);
    cudaGetSymbolAddress((void**)&q,    g_q);
    cudaGetSymbolAddress((void**)&k,    g_k);
    cudaGetSymbolAddress((void**)&v,    g_v);
    cudaGetSymbolAddress((void**)&vt,   g_vT);
    cudaGetSymbolAddress((void**)&sc,   g_sc);
    cudaGetSymbolAddress((void**)&scp,  g_scp);
    cudaGetSymbolAddress((void**)&attn, g_attn);
    cudaGetSymbolAddress((void**)&x1,   g_x1);
    cudaGetSymbolAddress((void**)&h2,   g_h2);
    cudaGetSymbolAddress((void**)&gate, g_gate);
    cudaGetSymbolAddress((void**)&ff,   g_ff);
    cudaGetSymbolAddress((void**)&rwq,  g_wq);
    cudaGetSymbolAddress((void**)&rwk,  g_wk);
    cudaGetSymbolAddress((void**)&rwv,  g_wv);
    cudaGetSymbolAddress((void**)&rwo,  g_wo);
    cudaGetSymbolAddress((void**)&rwg,  g_wg);
    cudaGetSymbolAddress((void**)&rwu,  g_wu);
    cudaGetSymbolAddress((void**)&rwd,  g_wd);

    cudaFuncSetAttribute(gemm_f16<0>, cudaFuncAttributeMaxDynamicSharedMemorySize, GEMM_SMEM_BYTES);
    cudaFuncSetAttribute(gemm_f16<1>, cudaFuncAttributeMaxDynamicSharedMemorySize, GEMM_SMEM_BYTES);

    const long long LTTDM = (long long)TT * DM;
    const long long LTTTT = (long long)TT * TT;

    // 0. convert all weights to fp16 (single launch)
    {
        int total = 4*S4 + 3*L4;
        cvt_all_kernel<<<total/256, 256>>>(wq, wk, wv, wo, wg, wu, wd,
                                           rwq, rwk, rwv, rwo, rwg, rwu, rwd);
    }

    // 1. h1 = half(LN1(x))
    ln_kernel<<<TOK, 256>>>(x, ln1w, ln1b, h1);

    // 2-4. Q, K, V projections (half outputs)
    {
        dim3 grid(DM/BN, TOK/BM, 1);
        gemm_f16<1><<<grid, 128, GEMM_SMEM_BYTES>>>(h1, rwq, q, nullptr, DM, DM, DM, DM,
                                        0,0, 0,0, 0,0, 1, 1.f, 0);
        gemm_f16<1><<<grid, 128, GEMM_SMEM_BYTES>>>(h1, rwk, k, nullptr, DM, DM, DM, DM,
                                        0,0, 0,0, 0,0, 1, 1.f, 0);
        gemm_f16<1><<<grid, 128, GEMM_SMEM_BYTES>>>(h1, rwv, v, nullptr, DM, DM, DM, DM,
                                        0,0, 0,0, 0,0, 1, 1.f, 0);
    }

    // 5. V^T per batch
    {
        dim3 grid(DM/32, TT/32, NB);
        dim3 blk(32, 8);
        transpose_v_kernel<<<grid, blk>>>(v, vt);
    }

    // 6. scores = Q @ K^T / sqrt(HD)  (fp32 out), z = b*16+h
    {
        dim3 grid(TT/BN, TT/BM, NB*NH);
        gemm_f16<0><<<grid, 128, GEMM_SMEM_BYTES>>>(q, k, sc, nullptr, HD, DM, DM, TT,
                                        (long long)HD, LTTDM,
                                        (long long)HD, LTTDM,
                                        LTTTT, 16*LTTTT,
                                        NH, 0.08838834764831845f, 0);
    }

    // 7. softmax -> half probs
    softmax_kernel<<<NB*NH*TT, 256>>>(sc, scp);

    // 8. attn = P @ V (half out)
    {
        dim3 grid(HD/BN, TT/BM, NB*NH);
        gemm_f16<1><<<grid, 128, GEMM_SMEM_BYTES>>>(scp, vt, attn, nullptr, TT, TT, TT, DM,
                                        LTTTT, 16*LTTTT,
                                        (long long)HD*TT, LTTDM,
                                        (long long)HD, LTTDM,
                                        NH, 1.f, 0);
    }

    // 9. x1 = x + attn @ wo^T (fp32 out + residual)
    {
        dim3 grid(DM/BN, TOK/BM, 1);
        gemm_f16<0><<<grid, 128, GEMM_SMEM_BYTES>>>(attn, rwo, x1, x, DM, DM, DM, DM,
                                        0,0, 0,0, 0,0, 1, 1.f, 1);
    }

    // 10. h2 = half(LN2(x1))
    ln_kernel<<<TOK, 256>>>(x1, ln2w, ln2b, h2);

    // 11. gate (fp32 out)
    {
        dim3 grid(DFF/BN, TOK/BM, 1);
        gemm_f16<0><<<grid, 128, GEMM_SMEM_BYTES>>>(h2, rwg, gate, nullptr, DM, DM, DM, DFF,
                                        0,0, 0,0, 0,0, 1, 1.f, 0);
        // 12. up + fused SwiGLU: ff = half(silu(gate) * up)
        gemm_f16<1><<<grid, 128, GEMM_SMEM_BYTES>>>(h2, rwu, ff, gate, DM, DM, DM, DFF,
                                        0,0, 0,0, 0,0, 1, 1.f, 2);
    }

    // 13. out = x1 + ff @ wd^T (fp32 out + residual)
    {
        dim3 grid(DM/BN, TOK/BM, 1);
        gemm_f16<0><<<grid, 128, GEMM_SMEM_BYTES>>>(ff, rwd, out, x1, DFF, DFF, DFF, DM,
                                        0,0, 0,0, 0,0, 1, 1.f, 1);
    }
}

// round 17
// speedup vs baseline: 1.2393x; 1.2393x over previous
#include <cuda_runtime.h>
#include <cuda_fp16.h>
#include <stdint.h>

// ---------------- problem constants ----------------
#define NB   2
#define TT   2048
#define DM   2048
#define NH   16
#define HD   128
#define DFF  8192
#define TOK  (NB*TT)

// ---------------- scratch (device globals) ----------------
__device__ __half g_h1  [(size_t)TOK*DM];
__device__ __half g_q   [(size_t)TOK*DM];
__device__ __half g_k   [(size_t)TOK*DM];
__device__ __half g_v   [(size_t)TOK*DM];
__device__ __half g_vT  [(size_t)TOK*DM];
__device__ float  g_sc  [(size_t)NB*NH*TT*TT];   // fp32 scores
__device__ __half g_scp [(size_t)NB*NH*TT*TT];   // fp16 probs
__device__ __half g_attn[(size_t)TOK*DM];
__device__ float  g_x1  [(size_t)TOK*DM];
__device__ __half g_h2  [(size_t)TOK*DM];
__device__ float  g_gate[(size_t)TOK*DFF];
__device__ __half g_ff  [(size_t)TOK*DFF];
__device__ __half g_wq[(size_t)DM*DM];
__device__ __half g_wk[(size_t)DM*DM];
__device__ __half g_wv[(size_t)DM*DM];
__device__ __half g_wo[(size_t)DM*DM];
__device__ __half g_wg[(size_t)DFF*DM];
__device__ __half g_wu[(size_t)DFF*DM];
__device__ __half g_wd[(size_t)DM*DFF];

// ---------------- helpers ----------------
__device__ __forceinline__ void cpasync16(void* dst, const void* src) {
    uint32_t s = (uint32_t)__cvta_generic_to_shared(dst);
    asm volatile("cp.async.cg.shared.global [%0], [%1], 16;\n" :: "r"(s), "l"(src));
}

__device__ __forceinline__ void ldsm_x4(uint32_t& r0, uint32_t& r1,
                                        uint32_t& r2, uint32_t& r3, uint32_t addr) {
    asm volatile("ldmatrix.sync.aligned.m8n8.x4.shared.b16 {%0,%1,%2,%3}, [%4];"
                 : "=r"(r0), "=r"(r1), "=r"(r2), "=r"(r3) : "r"(addr));
}

// ---------------- fp16 tensor-core GEMM ----------------
// 128x64 CTA tile, 128 threads (4 warps, each 32(M)x64(N)), 4 CTAs/SM.
// BK=64, double-buffered: ONE barrier per 64-K (half of R15's rate).
// C[m,n] = scale * sum_k A[m,k]*B[n,k]
// epi=1 (OUTH=0): += Res.   epi=2 (OUTH=1): C = silu(Res) * acc  (SwiGLU fuse)
#define BM  128
#define BN  64
#define BK  64
#define SROW 72                     // halves per smem row (64 + 8 pad)
#define ASTG_A (BM*SROW)            // 9216 halves
#define ASTG_B (BN*SROW)            // 4608 halves
#define STG_H  (ASTG_A + ASTG_B)    // 13824 halves per stage
#define NSTAGE 2
#define GEMM_SMEM_BYTES (NSTAGE*STG_H*2)   // 55,296 B

extern __shared__ __half s16[];

template<int OUTH>
__global__ __launch_bounds__(128, 4)
void gemm_f16(const __half* __restrict__ A, const __half* __restrict__ Bm,
              void* __restrict__ Cv, const float* __restrict__ Res,
              int K, int lda, int ldb, int ldc,
              long long zaLo, long long zaHi,
              long long zbLo, long long zbHi,
              long long zcLo, long long zcHi,
              int zdiv, float scale, int epi)
{
    long long zq = blockIdx.z / zdiv, zr = blockIdx.z % zdiv;
    A  += zq*zaHi + zr*zaLo;
    Bm += zq*zbHi + zr*zbLo;
    const long long coff = zq*zcHi + zr*zcLo;
    if (epi) Res += coff;

    const int m0 = blockIdx.y * BM;
    const int n0 = blockIdx.x * BN;

    const int tid  = threadIdx.x;
    const int lane = tid & 31;
    const int warp = tid >> 5;      // 0..3
    const int mb   = warp * 32;     // warp tile 32(M) x 64(N), nb = 0

    float acc[2][8][4];
#pragma unroll
    for (int i = 0; i < 2; i++)
#pragma unroll
        for (int j = 0; j < 8; j++)
#pragma unroll
            for (int l = 0; l < 4; l++) acc[i][j][l] = 0.f;

    const int nK = K / BK;   // >= 2 for all shapes here (QK: 128/64 = 2)

    // ldmatrix lane-address offsets (bytes) within a stage
    const uint32_t s16u = (uint32_t)__cvta_generic_to_shared(s16);
    const int lrow  = lane & 15;
    const int lchnk = (lane >> 4) * 8;
    const uint32_t aoff0 = (uint32_t)(((mb + lrow) * SROW + lchnk) * 2);
    const uint32_t aoff1 = aoff0 + 16 * SROW * 2;
    uint32_t boff[4];
#pragma unroll
    for (int p = 0; p < 4; p++)
        boff[p] = (uint32_t)(ASTG_A * 2 + ((p*16 + lrow) * SROW + lchnk) * 2);

    auto load_stage = [&](int st, int kt) {
        const int k0 = kt * BK;
        __half* sa = s16 + st * STG_H;
        __half* sb = sa + ASTG_A;
#pragma unroll
        for (int i = 0; i < 8; i++) {          // A: 128 rows x 8 chunks of 8 halves
            int idx = tid + i * 128;           // 0..1023
            int row = idx >> 3;
            int c8  = (idx & 7) << 3;
            cpasync16(&sa[row*SROW + c8], A + (size_t)(m0+row)*lda + k0 + c8);
        }
#pragma unroll
        for (int i = 0; i < 4; i++) {          // B: 64 rows x 8 chunks
            int idx = tid + i * 128;           // 0..511
            int row = idx >> 3;
            int c8  = (idx & 7) << 3;
            cpasync16(&sb[row*SROW + c8], Bm + (size_t)(n0+row)*ldb + k0 + c8);
        }
    };

    auto compute = [&](int slot) {
        const uint32_t stg = s16u + (uint32_t)(slot * STG_H * 2);
#pragma unroll
        for (int kk = 0; kk < BK; kk += 16) {
            const uint32_t kb = stg + kk * 2;
            uint32_t af[2][4];
            ldsm_x4(af[0][0], af[0][1], af[0][2], af[0][3], kb + aoff0);
            ldsm_x4(af[1][0], af[1][1], af[1][2], af[1][3], kb + aoff1);
            uint32_t bf[8][2];
#pragma unroll
            for (int p = 0; p < 4; p++) {
                ldsm_x4(bf[2*p][0], bf[2*p+1][0], bf[2*p][1], bf[2*p+1][1], kb + boff[p]);
            }
#pragma unroll
            for (int im = 0; im < 2; im++)
#pragma unroll
                for (int in = 0; in < 8; in++) {
                    asm volatile(
                        "mma.sync.aligned.m16n8k16.row.col.f32.f16.f16.f32 "
                        "{%0,%1,%2,%3}, {%4,%5,%6,%7}, {%8,%9}, {%0,%1,%2,%3};\n"
                        : "+f"(acc[im][in][0]), "+f"(acc[im][in][1]),
                          "+f"(acc[im][in][2]), "+f"(acc[im][in][3])
                        : "r"(af[im][0]), "r"(af[im][1]),
                          "r"(af[im][2]), "r"(af[im][3]),
                          "r"(bf[in][0]), "r"(bf[in][1]));
                }
        }
    };

    // prologue: stage 0 in flight
    load_stage(0, 0);
    asm volatile("cp.async.commit_group;\n");

    for (int kt = 0; kt < nK; kt++) {
        asm volatile("cp.async.wait_group 0;\n");   // stage kt landed (per-thread)
        __syncthreads();                            // publish; retires reads of other slot
        if (kt + 1 < nK) {
            load_stage((kt + 1) & 1, kt + 1);       // other slot: reads retired above
            asm volatile("cp.async.commit_group;\n");
        }
        compute(kt & 1);
    }

    // epilogue
#pragma unroll
    for (int im = 0; im < 2; im++) {
#pragma unroll
        for (int in = 0; in < 8; in++) {
            int r = m0 + mb + im*16 + (lane >> 2);
            int c = n0 + in*8 + ((lane & 3) << 1);
            float v0 = acc[im][in][0] * scale;
            float v1 = acc[im][in][1] * scale;
            float v2 = acc[im][in][2] * scale;
            float v3 = acc[im][in][3] * scale;
            if (OUTH) {
                if (epi == 2) {   // SwiGLU: C = silu(Res) * acc
                    float2 r0 = *(const float2*)&Res[(size_t)(r  )*ldc + c];
                    float2 r1 = *(const float2*)&Res[(size_t)(r+8)*ldc + c];
                    v0 *= r0.x / (1.f + __expf(-r0.x));
                    v1 *= r0.y / (1.f + __expf(-r0.y));
                    v2 *= r1.x / (1.f + __expf(-r1.x));
                    v3 *= r1.y / (1.f + __expf(-r1.y));
                }
                __half* C = (__half*)Cv + coff;
                *(__half2*)&C[(size_t)(r  )*ldc + c] = __floats2half2_rn(v0, v1);
                *(__half2*)&C[(size_t)(r+8)*ldc + c] = __floats2half2_rn(v2, v3);
            } else {
                float* C = (float*)Cv + coff;
                float2 t0 = {v0, v1}, t1 = {v2, v3};
                if (epi == 1) {
                    float2 r0 = *(const float2*)&Res[(size_t)(r  )*ldc + c];
                    float2 r1 = *(const float2*)&Res[(size_t)(r+8)*ldc + c];
                    t0.x += r0.x; t0.y += r0.y;
                    t1.x += r1.x; t1.y += r1.y;
                }
                *(float2*)&C[(size_t)(r  )*ldc + c] = t0;
                *(float2*)&C[(size_t)(r+8)*ldc + c] = t1;
            }
        }
    }
}

// ---------------- merged weight conversion f32 -> f16 ----------------
#define S4 (DM*DM/4)
#define L4 (DFF*DM/4)
__global__ __launch_bounds__(256)
void cvt_all_kernel(const float* __restrict__ wq, const float* __restrict__ wk,
                    const float* __restrict__ wv, const float* __restrict__ wo,
                    const float* __restrict__ wg, const float* __restrict__ wu,
                    const float* __restrict__ wd,
                    __half* __restrict__ oq, __half* __restrict__ ok,
                    __half* __restrict__ ov, __half* __restrict__ oo,
                    __half* __restrict__ og, __half* __restrict__ ou,
                    __half* __restrict__ od)
{
    int i = blockIdx.x * 256 + threadIdx.x;
    const float* src; __half* dst; int off;
    if (i < 4*S4) {
        int w = i / S4; off = i - w*S4;
        src = (w == 0) ? wq : (w == 1) ? wk : (w == 2) ? wv : wo;
        dst = (w == 0) ? oq : (w == 1) ? ok : (w == 2) ? ov : oo;
    } else {
        int j = i - 4*S4;
        int w = j / L4; off = j - w*L4;
        src = (w == 0) ? wg : (w == 1) ? wu : wd;
        dst = (w == 0) ? og : (w == 1) ? ou : od;
    }
    float4 v = ((const float4*)src)[off];
    ((__half2*)dst)[2*off    ] = __floats2half2_rn(v.x, v.y);
    ((__half2*)dst)[2*off + 1] = __floats2half2_rn(v.z, v.w);
}

// ---------------- LayerNorm (half output) ----------------
__global__ __launch_bounds__(256)
void ln_kernel(const float* __restrict__ x, const float* __restrict__ w,
               const float* __restrict__ b, __half* __restrict__ y)
{
    const int row = blockIdx.x;
    const float* xr = x + (size_t)row * DM;
    __half*      yr = y + (size_t)row * DM;

    float s = 0.f, sq = 0.f;
#pragma unroll
    for (int i = 0; i < DM/256; i++) {
        float v = xr[threadIdx.x + i*256];
        s += v; sq += v*v;
    }
#pragma unroll
    for (int o = 16; o; o >>= 1) {
        s  += __shfl_xor_sync(0xffffffffu, s,  o);
        sq += __shfl_xor_sync(0xffffffffu, sq, o);
    }
    __shared__ float sh[64];
    const int warp = threadIdx.x >> 5, lane = threadIdx.x & 31;
    if (lane == 0) { sh[warp] = s; sh[warp + 32] = sq; }
    __syncthreads();
    if (warp == 0) {
        s  = (lane < 8) ? sh[lane]      : 0.f;
        sq = (lane < 8) ? sh[lane + 32] : 0.f;
#pragma unroll
        for (int o = 4; o; o >>= 1) {
            s  += __shfl_xor_sync(0xffffffffu, s,  o);
            sq += __shfl_xor_sync(0xffffffffu, sq, o);
        }
        if (lane == 0) { sh[0] = s; sh[1] = sq; }
    }
    __syncthreads();
    const float mean = sh[0] * (1.f/DM);
    const float var  = sh[1] * (1.f/DM) - mean*mean;
    const float inv  = rsqrtf(var + 1e-5f);
#pragma unroll
    for (int i = 0; i < DM/256; i++) {
        int c = threadIdx.x + i*256;
        yr[c] = __float2half_rn((xr[c] - mean) * inv * w[c] + b[c]);
    }
}

// ---------------- softmax: fp32 scores -> fp16 probs ----------------
__global__ __launch_bounds__(256)
void softmax_kernel(const float* __restrict__ s, __half* __restrict__ p)
{
    const float* r = s + (size_t)blockIdx.x * TT;
    __half*      o = p + (size_t)blockIdx.x * TT;
    float v[TT/256];
    float mx = -1e30f;
#pragma unroll
    for (int i = 0; i < TT/256; i++) {
        v[i] = r[threadIdx.x + i*256];
        mx = fmaxf(mx, v[i]);
    }
#pragma unroll
    for (int ofs = 16; ofs; ofs >>= 1) mx = fmaxf(mx, __shfl_xor_sync(0xffffffffu, mx, ofs));
    __shared__ float sh[32];
    const int warp = threadIdx.x >> 5, lane = threadIdx.x & 31;
    if (lane == 0) sh[warp] = mx;
    __syncthreads();
    if (warp == 0) {
        mx = (lane < 8) ? sh[lane] : -1e30f;
#pragma unroll
        for (int ofs = 4; ofs; ofs >>= 1) mx = fmaxf(mx, __shfl_xor_sync(0xffffffffu, mx, ofs));
        if (lane == 0) sh[0] = mx;
    }
    __syncthreads();
    mx = sh[0];

    float sum = 0.f;
#pragma unroll
    for (int i = 0; i < TT/256; i++) { v[i] = __expf(v[i] - mx); sum += v[i]; }
#pragma unroll
    for (int ofs = 16; ofs; ofs >>= 1) sum += __shfl_xor_sync(0xffffffffu, sum, ofs);
    if (lane == 0) sh[warp] = sum;
    __syncthreads();
    if (warp == 0) {
        sum = (lane < 8) ? sh[lane] : 0.f;
#pragma unroll
        for (int ofs = 4; ofs; ofs >>= 1) sum += __shfl_xor_sync(0xffffffffu, sum, ofs);
        if (lane == 0) sh[0] = sum;
    }
    __syncthreads();
    const float inv = 1.f / sh[0];
#pragma unroll
    for (int i = 0; i < TT/256; i++)
        o[threadIdx.x + i*256] = __float2half_rn(v[i] * inv);
}

// ---------------- V -> V^T per batch (half) ----------------
__global__ void transpose_v_kernel(const __half* __restrict__ v, __half* __restrict__ vt)
{
    __shared__ __half tile[32][34];
    const int b  = blockIdx.z;
    const int x0 = blockIdx.x * 32;
    const int y0 = blockIdx.y * 32;
    const __half* vb = v  + (size_t)b * TT * DM;
    __half*      vtb = vt + (size_t)b * TT * DM;
    const int tx = threadIdx.x, ty = threadIdx.y;
#pragma unroll
    for (int i = 0; i < 32; i += 8)
        tile[ty + i][tx] = vb[(size_t)(y0 + ty + i) * DM + x0 + tx];
    __syncthreads();
#pragma unroll
    for (int i = 0; i < 32; i += 8)
        vtb[(size_t)(x0 + ty + i) * TT + y0 + tx] = tile[tx][ty + i];
}

// ---------------- launch ----------------
extern "C" void kernel_launch(void* const* d_in, const int* in_sizes, int n_in,
                              void* d_out, int out_size)
{
    const float* x     = (const float*)d_in[0];
    const float* wq    = (const float*)d_in[1];
    const float* wk    = (const float*)d_in[2];
    const float* wv    = (const float*)d_in[3];
    const float* wo    = (const float*)d_in[4];
    const float* wg    = (const float*)d_in[5];
    const float* wu    = (const float*)d_in[6];
    const float* wd    = (const float*)d_in[7];
    const float* ln1w  = (const float*)d_in[8];
    const float* ln1b  = (const float*)d_in[9];
    const float* ln2w  = (const float*)d_in[10];
    const float* ln2b  = (const float*)d_in[11];
    float* out = (float*)d_out;

    __half *h1, *q, *k, *v, *vt, *scp, *attn, *h2, *ff;
    float  *sc, *x1, *gate;
    __half *rwq, *rwk, *rwv, *rwo, *rwg, *rwu, *rwd;
    cudaGetSymbolAddress((void**)&h1,   g_h1);
    cudaGetSymbolAddress((void**)&q,    g_q);
    cudaGetSymbolAddress((void**)&k,    g_k);
    cudaGetSymbolAddress((void**)&v,    g_v);
    cudaGetSymbolAddress((void**)&vt,   g_vT);
    cudaGetSymbolAddress((void**)&sc,   g_sc);
    cudaGetSymbolAddress((void**)&scp,  g_scp);
    cudaGetSymbolAddress((void**)&attn, g_attn);
    cudaGetSymbolAddress((void**)&x1,   g_x1);
    cudaGetSymbolAddress((void**)&h2,   g_h2);
    cudaGetSymbolAddress((void**)&gate, g_gate);
    cudaGetSymbolAddress((void**)&ff,   g_ff);
    cudaGetSymbolAddress((void**)&rwq,  g_wq);
    cudaGetSymbolAddress((void**)&rwk,  g_wk);
    cudaGetSymbolAddress((void**)&rwv,  g_wv);
    cudaGetSymbolAddress((void**)&rwo,  g_wo);
    cudaGetSymbolAddress((void**)&rwg,  g_wg);
    cudaGetSymbolAddress((void**)&rwu,  g_wu);
    cudaGetSymbolAddress((void**)&rwd,  g_wd);

    cudaFuncSetAttribute(gemm_f16<0>, cudaFuncAttributeMaxDynamicSharedMemorySize, GEMM_SMEM_BYTES);
    cudaFuncSetAttribute(gemm_f16<1>, cudaFuncAttributeMaxDynamicSharedMemorySize, GEMM_SMEM_BYTES);

    const long long LTTDM = (long long)TT * DM;
    const long long LTTTT = (long long)TT * TT;

    // 0. convert all weights to fp16 (single launch)
    {
        int total = 4*S4 + 3*L4;
        cvt_all_kernel<<<total/256, 256>>>(wq, wk, wv, wo, wg, wu, wd,
                                           rwq, rwk, rwv, rwo, rwg, rwu, rwd);
    }

    // 1. h1 = half(LN1(x))
    ln_kernel<<<TOK, 256>>>(x, ln1w, ln1b, h1);

    // 2-4. Q, K, V projections (half outputs)
    {
        dim3 grid(DM/BN, TOK/BM, 1);
        gemm_f16<1><<<grid, 128, GEMM_SMEM_BYTES>>>(h1, rwq, q, nullptr, DM, DM, DM, DM,
                                        0,0, 0,0, 0,0, 1, 1.f, 0);
        gemm_f16<1><<<grid, 128, GEMM_SMEM_BYTES>>>(h1, rwk, k, nullptr, DM, DM, DM, DM,
                                        0,0, 0,0, 0,0, 1, 1.f, 0);
        gemm_f16<1><<<grid, 128, GEMM_SMEM_BYTES>>>(h1, rwv, v, nullptr, DM, DM, DM, DM,
                                        0,0, 0,0, 0,0, 1, 1.f, 0);
    }

    // 5. V^T per batch
    {
        dim3 grid(DM/32, TT/32, NB);
        dim3 blk(32, 8);
        transpose_v_kernel<<<grid, blk>>>(v, vt);
    }

    // 6. scores = Q @ K^T / sqrt(HD)  (fp32 out), z = b*16+h
    {
        dim3 grid(TT/BN, TT/BM, NB*NH);
        gemm_f16<0><<<grid, 128, GEMM_SMEM_BYTES>>>(q, k, sc, nullptr, HD, DM, DM, TT,
                                        (long long)HD, LTTDM,
                                        (long long)HD, LTTDM,
                                        LTTTT, 16*LTTTT,
                                        NH, 0.08838834764831845f, 0);
    }

    // 7. softmax -> half probs
    softmax_kernel<<<NB*NH*TT, 256>>>(sc, scp);

    // 8. attn = P @ V (half out)
    {
        dim3 grid(HD/BN, TT/BM, NB*NH);
        gemm_f16<1><<<grid, 128, GEMM_SMEM_BYTES>>>(scp, vt, attn, nullptr, TT, TT, TT, DM,
                                        LTTTT, 16*LTTTT,
                                        (long long)HD*TT, LTTDM,
                                        (long long)HD, LTTDM,
                                        NH, 1.f, 0);
    }

    // 9. x1 = x + attn @ wo^T (fp32 out + residual)
    {
        dim3 grid(DM/BN, TOK/BM, 1);
        gemm_f16<0><<<grid, 128, GEMM_SMEM_BYTES>>>(attn, rwo, x1, x, DM, DM, DM, DM,
                                        0,0, 0,0, 0,0, 1, 1.f, 1);
    }

    // 10. h2 = half(LN2(x1))
    ln_kernel<<<TOK, 256>>>(x1, ln2w, ln2b, h2);

    // 11. gate (fp32 out)
    {
        dim3 grid(DFF/BN, TOK/BM, 1);
        gemm_f16<0><<<grid, 128, GEMM_SMEM_BYTES>>>(h2, rwg, gate, nullptr, DM, DM, DM, DFF,
                                        0,0, 0,0, 0,0, 1, 1.f, 0);
        // 12. up + fused SwiGLU: ff = half(silu(gate) * up)
        gemm_f16<1><<<grid, 128, GEMM_SMEM_BYTES>>>(h2, rwu, ff, gate, DM, DM, DM, DFF,
                                        0,0, 0,0, 0,0, 1, 1.f, 2);
    }

    // 13. out = x1 + ff @ wd^T (fp32 out + residual)
    {
        dim3 grid(DM/BN, TOK/BM, 1);
        gemm_f16<0><<<grid, 128, GEMM_SMEM_BYTES>>>(ff, rwd, out, x1, DFF, DFF, DFF, DM,
                                        0,0, 0,0, 0,0, 1, 1.f, 1);
    }
}